// round 1
// baseline (speedup 1.0000x reference)
#include <cuda_runtime.h>

// Problem shapes (fixed by setup_inputs)
#define B_ 64
#define T_ 4096
#define F_ 64
#define H_ 256
#define EPSV 1e-8f

// Chunked-scan parallelization: lambda=0.5 => cold-start warm-up of 32 steps
// leaves state error ~0.5^32 ~ 2e-10, far below the 1e-3 tolerance.
#define CHUNK 128
#define NCHUNK (T_ / CHUNK)   // 32
#define WARM 32

// Scratch (no allocations allowed): 1 MB fgsum + global double accumulator.
__device__ double g_acc;
__device__ float g_fgsum[B_ * T_];

__global__ void k_init() { g_acc = 0.0; }

// ---------------------------------------------------------------------------
// fgsum[b*T+t] = sum_h forget_gates[b,t,h].  One warp per 1KB row, float4.
// Dominant HBM read (268 MB).
// ---------------------------------------------------------------------------
__global__ void k_fgsum(const float4* __restrict__ fg) {
    int warp = (blockIdx.x * blockDim.x + threadIdx.x) >> 5;
    int lane = threadIdx.x & 31;
    if (warp >= B_ * T_) return;
    const float4* row = fg + (size_t)warp * (H_ / 4);
    float4 a = row[lane];
    float4 b = row[lane + 32];
    float s = (a.x + a.y) + (a.z + a.w) + (b.x + b.y) + (b.z + b.w);
#pragma unroll
    for (int o = 16; o > 0; o >>= 1) s += __shfl_xor_sync(0xffffffffu, s, o);
    if (lane == 0) g_fgsum[warp] = s;
}

// ---------------------------------------------------------------------------
// MSE over B*T elements, accumulated (scaled) into g_acc.
// ---------------------------------------------------------------------------
__global__ void k_mse(const float4* __restrict__ in, const float4* __restrict__ tg, int n4) {
    float acc = 0.f;
    for (int i = blockIdx.x * blockDim.x + threadIdx.x; i < n4; i += gridDim.x * blockDim.x) {
        float4 a = in[i], b = tg[i];
        float dx = a.x - b.x, dy = a.y - b.y, dz = a.z - b.z, dw = a.w - b.w;
        acc += dx * dx + dy * dy + dz * dz + dw * dw;
    }
#pragma unroll
    for (int o = 16; o > 0; o >>= 1) acc += __shfl_xor_sync(0xffffffffu, acc, o);
    __shared__ float sh[32];
    int lane = threadIdx.x & 31, wid = threadIdx.x >> 5;
    if (lane == 0) sh[wid] = acc;
    __syncthreads();
    if (threadIdx.x == 0) {
        float s = 0.f;
        int nw = blockDim.x >> 5;
        for (int w = 0; w < nw; ++w) s += sh[w];
        atomicAdd(&g_acc, (double)s * (1.0 / ((double)B_ * T_)));
    }
}

// ---------------------------------------------------------------------------
// Chunked EW autocorrelation scan.
// Block = (b, chunk); thread f in [0,64): coalesced 256B per timestep.
// Each thread accumulates sum_t (1 - |ac|) * fgsum[b,t] over its chunk.
// t=0 pad contributes irr=1 -> + fgsum[b,0] per f-thread (scale absorbs /F).
// ---------------------------------------------------------------------------
__global__ void __launch_bounds__(F_) k_scan(const float* __restrict__ seq) {
    int b = blockIdx.x / NCHUNK;
    int chunk = blockIdx.x % NCHUNK;
    int f = threadIdx.x;
    const float* base = seq + (size_t)b * T_ * F_ + f;
    const float* fgs = g_fgsum + b * T_;

    int t0 = chunk * CHUNK;
    int ts = (chunk == 0) ? 1 : (t0 - WARM);

    float m = 0.f, v = EPSV, c = 0.f;
    float xl = __ldg(base + (size_t)(ts - 1) * F_);
    float acc = (chunk == 0) ? __ldg(fgs + 0) : 0.f;   // t = 0 pad term

    // warm-up (no accumulation) — runs only for chunk > 0
#pragma unroll 4
    for (int t = ts; t < t0; ++t) {
        float xt = __ldg(base + (size_t)t * F_);
        m = 0.5f * (m + xt);
        float d = xt - m;
        v = 0.5f * (v + d * d);
        c = 0.5f * (c + d * (xl - m));
        xl = xt;
    }

    int tb = (chunk == 0) ? 1 : t0;
#pragma unroll 4
    for (int t = tb; t < t0 + CHUNK; ++t) {
        float xt = __ldg(base + (size_t)t * F_);
        m = 0.5f * (m + xt);
        float d = xt - m;
        v = 0.5f * (v + d * d);
        c = 0.5f * (c + d * (xl - m));
        xl = xt;
        float ac = c * rsqrtf(v * v + EPSV);
        acc += (1.0f - fabsf(ac)) * __ldg(fgs + t);
    }

#pragma unroll
    for (int o = 16; o > 0; o >>= 1) acc += __shfl_xor_sync(0xffffffffu, acc, o);
    __shared__ float sh[2];
    if ((threadIdx.x & 31) == 0) sh[threadIdx.x >> 5] = acc;
    __syncthreads();
    if (threadIdx.x == 0) {
        double s = (double)sh[0] + (double)sh[1];
        // ALPHA / (B*T*H*F)
        atomicAdd(&g_acc, s * (0.5 / ((double)B_ * T_ * H_ * F_)));
    }
}

__global__ void k_final(float* out) { out[0] = (float)g_acc; }

// ---------------------------------------------------------------------------
extern "C" void kernel_launch(void* const* d_in, const int* in_sizes, int n_in,
                              void* d_out, int out_size) {
    const float* input  = (const float*)d_in[0];
    const float* target = (const float*)d_in[1];
    const float* seq    = (const float*)d_in[2];
    const float* fg     = (const float*)d_in[3];
    float* out = (float*)d_out;

    k_init<<<1, 1>>>();

    // one warp per (b,t) row of forget_gates: B*T warps
    int rows = B_ * T_;
    int blocks_fg = (rows * 32 + 255) / 256;
    k_fgsum<<<blocks_fg, 256>>>((const float4*)fg);

    k_mse<<<128, 256>>>((const float4*)input, (const float4*)target, (B_ * T_) / 4);

    k_scan<<<B_ * NCHUNK, F_>>>(seq);

    k_final<<<1, 1>>>(out);
}

// round 2
// speedup vs baseline: 1.1986x; 1.1986x over previous
#include <cuda_runtime.h>

// Shapes fixed by setup_inputs
#define B_ 64
#define T_ 4096
#define F_ 64
#define H_ 256
#define EPSV 1e-8f

// Chunked scan: lambda=0.5 -> 32-step warm-up leaves state error ~0.5^32.
#define CHUNK 128
#define NCHUNK (T_ / CHUNK)        // 32
#define WARM 32

#define NS (B_ * NCHUNK)           // 2048 scan blocks
#define NM 16                      // mse blocks
#define NB (NS + NM)

// Per-block partials (pre-scaled); finalize sums in double. No allocations.
__device__ float g_part[NB];

// ---------------------------------------------------------------------------
// Fused kernel. Block role by blockIdx.x:
//  [0, NS):  (b, chunk) blocks. Phase 1: reduce own 128x256 forget_gates slice
//            into smem fgsum (warp-per-row, float4, 2 rows in flight).
//            Phase 2: EW autocorr scan over seq chunk, dotted with smem fgsum.
//  [NS, NB): MSE partial blocks (grid-stride float4).
// ---------------------------------------------------------------------------
__global__ void __launch_bounds__(64) k_main(const float* __restrict__ seq,
                                             const float4* __restrict__ fg,
                                             const float4* __restrict__ inp,
                                             const float4* __restrict__ tgt) {
    __shared__ float fgsum_s[CHUNK];
    __shared__ float sh[2];

    if (blockIdx.x < NS) {
        int b = blockIdx.x / NCHUNK;
        int chunk = blockIdx.x % NCHUNK;
        int t0 = chunk * CHUNK;
        int warp = threadIdx.x >> 5, lane = threadIdx.x & 31;

        // ---- Phase 1: fgsum for this chunk's 128 timesteps (BW-heavy) ----
        const float4* fgb = fg + (size_t)(b * T_ + t0) * (H_ / 4);
        int r0 = warp * (CHUNK / 2);               // 64 rows per warp
        for (int r = r0; r < r0 + CHUNK / 2; r += 2) {
            const float4* ra = fgb + (size_t)r * (H_ / 4);
            const float4* rb = ra + (H_ / 4);
            float4 a0 = ra[lane], a1 = ra[lane + 32];
            float4 b0 = rb[lane], b1 = rb[lane + 32];
            float s0 = (a0.x + a0.y) + (a0.z + a0.w) + (a1.x + a1.y) + (a1.z + a1.w);
            float s1 = (b0.x + b0.y) + (b0.z + b0.w) + (b1.x + b1.y) + (b1.z + b1.w);
#pragma unroll
            for (int o = 16; o > 0; o >>= 1) {
                s0 += __shfl_xor_sync(0xffffffffu, s0, o);
                s1 += __shfl_xor_sync(0xffffffffu, s1, o);
            }
            if (lane == 0) { fgsum_s[r] = s0; fgsum_s[r + 1] = s1; }
        }
        __syncthreads();

        // ---- Phase 2: EW autocorrelation scan (latency-heavy) ----
        int f = threadIdx.x;
        const float* base = seq + (size_t)b * T_ * F_ + f;

        int ts = (chunk == 0) ? 1 : (t0 - WARM);
        float m = 0.f, v = EPSV, c = 0.f;
        float xl = __ldg(base + (size_t)(ts - 1) * F_);
        float acc = (chunk == 0) ? fgsum_s[0] : 0.f;   // t=0 pad: irr==1

        // warm-up, no accumulation (chunk > 0 only)
#pragma unroll 8
        for (int t = ts; t < t0; ++t) {
            float xt = __ldg(base + (size_t)t * F_);
            m = 0.5f * (m + xt);
            float d = xt - m;
            v = 0.5f * (v + d * d);
            c = 0.5f * (c + d * (xl - m));
            xl = xt;
        }

        int tb = (chunk == 0) ? 1 : t0;
#pragma unroll 8
        for (int t = tb; t < t0 + CHUNK; ++t) {
            float xt = __ldg(base + (size_t)t * F_);
            m = 0.5f * (m + xt);
            float d = xt - m;
            v = 0.5f * (v + d * d);
            c = 0.5f * (c + d * (xl - m));
            xl = xt;
            float ac = c * rsqrtf(v * v + EPSV);
            acc += (1.0f - fabsf(ac)) * fgsum_s[t - t0];
        }

#pragma unroll
        for (int o = 16; o > 0; o >>= 1) acc += __shfl_xor_sync(0xffffffffu, acc, o);
        if (lane == 0) sh[warp] = acc;
        __syncthreads();
        if (threadIdx.x == 0) {
            // ALPHA / (B*T*H*F) = 0.5 / 2^32
            g_part[blockIdx.x] = (sh[0] + sh[1]) * (0.5f / 4294967296.0f);
        }
    } else {
        // ---- MSE role ----
        int bid = blockIdx.x - NS;
        const int n4 = (B_ * T_) / 4;
        float acc = 0.f;
        for (int i = bid * 64 + threadIdx.x; i < n4; i += NM * 64) {
            float4 a = inp[i], b = tgt[i];
            float dx = a.x - b.x, dy = a.y - b.y, dz = a.z - b.z, dw = a.w - b.w;
            acc += dx * dx + dy * dy + dz * dz + dw * dw;
        }
#pragma unroll
        for (int o = 16; o > 0; o >>= 1) acc += __shfl_xor_sync(0xffffffffu, acc, o);
        if ((threadIdx.x & 31) == 0) sh[threadIdx.x >> 5] = acc;
        __syncthreads();
        if (threadIdx.x == 0)
            g_part[blockIdx.x] = (sh[0] + sh[1]) * (1.0f / ((float)B_ * T_));
    }
}

// ---------------------------------------------------------------------------
__global__ void k_final(float* __restrict__ out) {
    __shared__ double sd[8];
    double s = 0.0;
    for (int i = threadIdx.x; i < NB; i += 256) s += (double)g_part[i];
#pragma unroll
    for (int o = 16; o > 0; o >>= 1) s += __shfl_xor_sync(0xffffffffu, s, o);
    if ((threadIdx.x & 31) == 0) sd[threadIdx.x >> 5] = s;
    __syncthreads();
    if (threadIdx.x == 0) {
        double tot = 0.0;
        for (int w = 0; w < 8; ++w) tot += sd[w];
        out[0] = (float)tot;
    }
}

// ---------------------------------------------------------------------------
extern "C" void kernel_launch(void* const* d_in, const int* in_sizes, int n_in,
                              void* d_out, int out_size) {
    const float* input  = (const float*)d_in[0];
    const float* target = (const float*)d_in[1];
    const float* seq    = (const float*)d_in[2];
    const float* fg     = (const float*)d_in[3];

    k_main<<<NB, 64>>>(seq, (const float4*)fg,
                       (const float4*)input, (const float4*)target);
    k_final<<<1, 256>>>((float*)d_out);
}